// round 16
// baseline (speedup 1.0000x reference)
#include <cuda_runtime.h>
#include <cuda_bf16.h>
#include <cuda_fp16.h>
#include <cstdint>

#define N_NODES 50000
#define N_EDGES 800000
#define IN_DIM 64
#define HID 128
#define NUM_LAYERS 4
#define NUM_GRAPHS 128

// ---------------- scratch (device globals; no allocation allowed) ----------------
__device__ __align__(16) float g_h[N_NODES * HID];     // node features (f32, authoritative)
__device__ __align__(16) uint2 g_h16[N_NODES * 32];    // fp16 copy for gather (half2x2/lane)
__device__ __align__(16) float g_aggr[N_NODES * HID];  // edge aggregation; reused as z
__device__ __align__(16) float g_vn[NUM_GRAPHS * HID];
__device__ __align__(16) float g_vnup[NUM_GRAPHS * HID];
__device__ double g_bnsum[NUM_LAYERS * HID];           // per-layer slots
__device__ double g_bnsq[NUM_LAYERS * HID];
__device__ __align__(16) float g_gsum[NUM_GRAPHS * HID];
__device__ int g_gcnt[NUM_GRAPHS];
// CSR (by destination) built once per call.
// g_deg: starts all-zero (static init call 1; re-zeroed by k_cls at end of each call)
__device__ int g_deg[N_NODES];
__device__ int g_rowptr[N_NODES + 1];
__device__ __align__(16) int4 g_edge[N_EDGES];  // {src|batch<<17, ax_bits, ay_bits, 0}
// pre-packed bf16 hi/lo weights: [mat 0..8][part 0..1][8192]  (mat 8 = W_in, 4096 used)
__device__ __align__(16) uint32_t g_wpack[9 * 2 * 8192];

__device__ __forceinline__ void red_add_v4(float* addr, float4 v) {
    asm volatile("red.global.add.v4.f32 [%0], {%1,%2,%3,%4};"
                 :: "l"(addr), "f"(v.x), "f"(v.y), "f"(v.z), "f"(v.w) : "memory");
}

// pack two f32 -> bf16x2 (e0 -> low half / smaller k, e1 -> high half)
__device__ __forceinline__ uint32_t pack2(float e0, float e1) {
    uint32_t r;
    asm("cvt.rn.bf16x2.f32 %0, %1, %2;" : "=r"(r) : "f"(e1), "f"(e0));
    return r;
}
// bf16 round-trip (keeps hi part as f32)
__device__ __forceinline__ float bfr(float x) {
    return __bfloat162float(__float2bfloat16_rn(x));
}
// pack two f32 -> fp16x2
__device__ __forceinline__ uint32_t packh2(float e0, float e1) {
    __half2 h = __floats2half2_rn(e0, e1);
    return *(uint32_t*)&h;
}
__device__ __forceinline__ float4 unpackh4(uint2 v) {
    float2 a = __half22float2(*(__half2*)&v.x);
    float2 b = __half22float2(*(__half2*)&v.y);
    return make_float4(a.x, a.y, b.x, b.y);
}

__device__ __forceinline__ void mma16(float* c, uint32_t a0, uint32_t a1, uint32_t a2,
                                      uint32_t a3, uint32_t b0, uint32_t b1) {
    asm volatile(
        "mma.sync.aligned.m16n8k16.row.col.f32.bf16.bf16.f32 "
        "{%0,%1,%2,%3}, {%4,%5,%6,%7}, {%8,%9}, {%0,%1,%2,%3};\n"
        : "+f"(c[0]), "+f"(c[1]), "+f"(c[2]), "+f"(c[3])
        : "r"(a0), "r"(a1), "r"(a2), "r"(a3), "r"(b0), "r"(b1));
}

// ================= weight pre-pack: 8 layer mats + W_in -> bf16 hi/lo pairs ========
__global__ void k_wprep(const float* __restrict__ cW1, const float* __restrict__ cW2,
                        const float* __restrict__ Win) {
    int mat = blockIdx.x;              // 0..7: layer*2+(0=W1,1=W2); 8: W_in
    int tid = threadIdx.x;
    if (mat < 8) {
        int L = mat >> 1;
        const float* W = (mat & 1) ? (cW2 + L * HID * HID) : (cW1 + L * HID * HID);
        uint32_t* dsth = g_wpack + (mat * 2 + 0) * 8192;
        uint32_t* dstl = g_wpack + (mat * 2 + 1) * 8192;
#pragma unroll
        for (int i = 0; i < 32; i++) {
            int flat = i * 256 + tid;      // 0..8191 = kp*128 + n
            int kp = flat >> 7, n = flat & 127;
            float w0 = W[(2 * kp) * HID + n];
            float w1 = W[(2 * kp + 1) * HID + n];
            float h0 = bfr(w0), h1 = bfr(w1);
            dsth[flat] = pack2(h0, h1);
            dstl[flat] = pack2(w0 - h0, w1 - h1);
        }
    } else {
        uint32_t* dsth = g_wpack + (8 * 2 + 0) * 8192;
        uint32_t* dstl = g_wpack + (8 * 2 + 1) * 8192;
#pragma unroll
        for (int i = 0; i < 16; i++) {
            int flat = i * 256 + tid;      // 0..4095 = kp*128 + n
            int kp = flat >> 7, n = flat & 127;
            float w0 = Win[(2 * kp) * HID + n];
            float w1 = Win[(2 * kp + 1) * HID + n];
            float h0 = bfr(w0), h1 = bfr(w1);
            dsth[flat] = pack2(h0, h1);
            dstl[flat] = pack2(w0 - h0, w1 - h1);
        }
    }
}

// ================= CSR build =================
__global__ void k_hist(const int* __restrict__ ei) {
    int e = blockIdx.x * 256 + threadIdx.x;   // grid exactly N_EDGES/256
    atomicAdd(&g_deg[ei[N_EDGES + e]], 1);
}

__global__ void k_scan() {
    __shared__ int sums[1024];
    int tid = threadIdx.x;
    const int CH = (N_NODES + 1023) / 1024;   // 49
    int st = tid * CH;
    int en = st + CH; if (en > N_NODES) en = N_NODES;
    int s = 0;
    for (int i = st; i < en; i++) s += g_deg[i];
    sums[tid] = s;
    __syncthreads();
    for (int off = 1; off < 1024; off <<= 1) {
        int v = (tid >= off) ? sums[tid - off] : 0;
        __syncthreads();
        sums[tid] += v;
        __syncthreads();
    }
    int run = sums[tid] - s;
    for (int i = st; i < en; i++) {
        int c = g_deg[i];
        g_rowptr[i] = run;
        g_deg[i] = run;     // cursor for scatter
        run += c;
    }
    if (tid == 1023) g_rowptr[N_NODES] = N_EDGES;
}

// 2 edges per thread (MLP=2 on the atomic-cursor chain)
__global__ void k_scatter(const int* __restrict__ ei, const float* __restrict__ ea,
                          const int* __restrict__ batch) {
    int e0 = blockIdx.x * 512 + threadIdx.x;
    int e1 = e0 + 256;
    if (e0 < N_EDGES) {
        int d = ei[N_EDGES + e0];
        int s = ei[e0];
        float2 a = ((const float2*)ea)[e0];
        int pos = atomicAdd(&g_deg[d], 1);
        g_edge[pos] = make_int4(s | (batch[s] << 17),
                                __float_as_int(a.x), __float_as_int(a.y), 0);
    }
    if (e1 < N_EDGES) {
        int d = ei[N_EDGES + e1];
        int s = ei[e1];
        float2 a = ((const float2*)ea)[e1];
        int pos = atomicAdd(&g_deg[d], 1);
        g_edge[pos] = make_int4(s | (batch[s] << 17),
                                __float_as_int(a.x), __float_as_int(a.y), 0);
    }
}

// ======== input projection via 3xBF16 MMA: h = x @ W_in + b_in (+ aux init) ========
#define UA2_STRIDE 36   // uint32 words per x-pair row (64 feats = 32 pairs + pad)
#define WB_STRIDE 136   // uint32 words per W-kpair row
#define USH2_OFF 0
#define USL2_OFF (64 * UA2_STRIDE)
#define WPH2_OFF (2 * 64 * UA2_STRIDE)
#define WPL2_OFF (WPH2_OFF + 32 * WB_STRIDE)
#define SMEM_IN_WORDS (WPL2_OFF + 32 * WB_STRIDE)
#define SMEM_IN_BYTES (SMEM_IN_WORDS * 4)      // 53248 B

__global__ void __launch_bounds__(256) k_input_mma(const float* __restrict__ x,
                                                   const float* __restrict__ bin) {
    extern __shared__ uint32_t smw[];
    uint32_t* ush = smw + USH2_OFF;
    uint32_t* usl = smw + USL2_OFF;
    uint32_t* wph = smw + WPH2_OFF;
    uint32_t* wpl = smw + WPL2_OFF;
    int tid = threadIdx.x;
    int base = blockIdx.x * 64;
    int w = tid >> 5, lane = tid & 31;
    int gid = lane >> 2, tig = lane & 3;
    int mbase = (w & 3) * 16, nbase = (w >> 2) * 64;

    if (blockIdx.x == 0) {
        for (int i = tid; i < NUM_GRAPHS * HID; i += 256) {
            g_vn[i] = 0.f; g_vnup[i] = 0.f; g_gsum[i] = 0.f;
        }
        if (tid < HID) {
#pragma unroll
            for (int l = 0; l < NUM_LAYERS; l++) {
                g_bnsum[l * HID + tid] = 0.0;
                g_bnsq[l * HID + tid] = 0.0;
            }
        }
        if (tid < NUM_GRAPHS) g_gcnt[tid] = 0;
    }

    const float4* x4 = (const float4*)x;
#pragma unroll
    for (int i = 0; i < 4; i++) {
        int idx = i * 256 + tid;       // float4 index within 64x16
        int n = idx >> 4, c4 = idx & 15;
        float4 v = make_float4(0.f, 0.f, 0.f, 0.f);
        if (base + n < N_NODES) v = x4[(base + n) * 16 + c4];
        float hx = bfr(v.x), hy = bfr(v.y), hz = bfr(v.z), hw = bfr(v.w);
        int p = n * UA2_STRIDE + 2 * c4;
        ush[p]     = pack2(hx, hy);
        ush[p + 1] = pack2(hz, hw);
        usl[p]     = pack2(v.x - hx, v.y - hy);
        usl[p + 1] = pack2(v.z - hz, v.w - hw);
    }
    {
        const uint4* srch = (const uint4*)(g_wpack + (8 * 2 + 0) * 8192);
        const uint4* srcl = (const uint4*)(g_wpack + (8 * 2 + 1) * 8192);
#pragma unroll
        for (int i = 0; i < 4; i++) {
            int f4 = i * 256 + tid;        // uint4 index 0..1023
            int kp = f4 >> 5;
            int n0 = (f4 & 31) * 4;
            *(uint4*)(wph + kp * WB_STRIDE + n0) = srch[f4];
            *(uint4*)(wpl + kp * WB_STRIDE + n0) = srcl[f4];
        }
    }
    __syncthreads();

    float c[8][4];
#pragma unroll
    for (int j = 0; j < 8; j++)
#pragma unroll
        for (int q = 0; q < 4; q++) c[j][q] = 0.f;

#pragma unroll
    for (int k0 = 0; k0 < 4; k0++) {
        int kb = k0 * 8;
        uint32_t ah0 = ush[(mbase + gid) * UA2_STRIDE + kb + tig];
        uint32_t ah1 = ush[(mbase + gid + 8) * UA2_STRIDE + kb + tig];
        uint32_t ah2 = ush[(mbase + gid) * UA2_STRIDE + kb + tig + 4];
        uint32_t ah3 = ush[(mbase + gid + 8) * UA2_STRIDE + kb + tig + 4];
        uint32_t al0 = usl[(mbase + gid) * UA2_STRIDE + kb + tig];
        uint32_t al1 = usl[(mbase + gid + 8) * UA2_STRIDE + kb + tig];
        uint32_t al2 = usl[(mbase + gid) * UA2_STRIDE + kb + tig + 4];
        uint32_t al3 = usl[(mbase + gid + 8) * UA2_STRIDE + kb + tig + 4];
#pragma unroll
        for (int j = 0; j < 8; j++) {
            int col = nbase + 8 * j + gid;
            uint32_t bh0 = wph[(kb + tig) * WB_STRIDE + col];
            uint32_t bh1 = wph[(kb + tig + 4) * WB_STRIDE + col];
            uint32_t bl0 = wpl[(kb + tig) * WB_STRIDE + col];
            uint32_t bl1 = wpl[(kb + tig + 4) * WB_STRIDE + col];
            mma16(c[j], ah0, ah1, ah2, ah3, bh0, bh1);
            mma16(c[j], al0, al1, al2, al3, bh0, bh1);
            mma16(c[j], ah0, ah1, ah2, ah3, bl0, bl1);
        }
    }

    int r0 = base + mbase + gid;
    int r1 = r0 + 8;
    bool v0 = r0 < N_NODES, v1 = r1 < N_NODES;
#pragma unroll
    for (int j = 0; j < 8; j++) {
        int col = nbase + 8 * j + 2 * tig;
        float2 bb = *(const float2*)(bin + col);
        float z0 = c[j][0] + bb.x, z1 = c[j][1] + bb.y;
        float z2 = c[j][2] + bb.x, z3 = c[j][3] + bb.y;
        if (v0) {
            *(float2*)(g_h + r0 * HID + col) = make_float2(z0, z1);
            *(uint32_t*)((uint32_t*)g_h16 + r0 * 64 + (col >> 1)) = packh2(z0, z1);
        }
        if (v1) {
            *(float2*)(g_h + r1 * HID + col) = make_float2(z2, z3);
            *(uint32_t*)((uint32_t*)g_h16 + r1 * 64 + (col >> 1)) = packh2(z2, z3);
        }
    }
}

// ============ edge gather (fp16 h): aggr[n] = sum relu(h[src]+vn[b[src]]+e) ========
// one warp per node, CSR lists; int4 edge records; 4-way edge unroll for MLP=4.
template <int USE_VN>
__global__ void __launch_bounds__(256) k_gather(const float* __restrict__ We,
                                                const float* __restrict__ be) {
    int lane = threadIdx.x & 31;
    int n = (blockIdx.x * 256 + threadIdx.x) >> 5;   // grid exactly N_NODES warps
    float4 w0 = ((const float4*)We)[lane];
    float4 w1 = ((const float4*)(We + HID))[lane];
    float4 bb = ((const float4*)be)[lane];
    int start = g_rowptr[n];
    int end = g_rowptr[n + 1];
    float4 acc = make_float4(0.f, 0.f, 0.f, 0.f);
    const uint2* h16 = g_h16;
    const float4* vn4 = (const float4*)g_vn;
    for (int base = start; base < end; base += 32) {
        int idx = base + lane;
        int p = 0;
        float ax = 0.f, ay = 0.f;
        if (idx < end) {
            int4 ev = __ldg(&g_edge[idx]);
            p = ev.x; ax = __int_as_float(ev.y); ay = __int_as_float(ev.z);
        }
        int cnt = end - base; if (cnt > 32) cnt = 32;
        int j = 0;
        for (; j + 3 < cnt; j += 4) {
            int pj0 = __shfl_sync(0xffffffffu, p, j);
            float ax0 = __shfl_sync(0xffffffffu, ax, j);
            float ay0 = __shfl_sync(0xffffffffu, ay, j);
            int pj1 = __shfl_sync(0xffffffffu, p, j + 1);
            float ax1 = __shfl_sync(0xffffffffu, ax, j + 1);
            float ay1 = __shfl_sync(0xffffffffu, ay, j + 1);
            int pj2 = __shfl_sync(0xffffffffu, p, j + 2);
            float ax2 = __shfl_sync(0xffffffffu, ax, j + 2);
            float ay2 = __shfl_sync(0xffffffffu, ay, j + 2);
            int pj3 = __shfl_sync(0xffffffffu, p, j + 3);
            float ax3 = __shfl_sync(0xffffffffu, ax, j + 3);
            float ay3 = __shfl_sync(0xffffffffu, ay, j + 3);
            uint2 q0 = __ldg(&h16[(pj0 & 0x1FFFF) * 32 + lane]);
            uint2 q1 = __ldg(&h16[(pj1 & 0x1FFFF) * 32 + lane]);
            uint2 q2 = __ldg(&h16[(pj2 & 0x1FFFF) * 32 + lane]);
            uint2 q3 = __ldg(&h16[(pj3 & 0x1FFFF) * 32 + lane]);
            float4 h0 = unpackh4(q0);
            float4 h1 = unpackh4(q1);
            float4 h2 = unpackh4(q2);
            float4 h3 = unpackh4(q3);
            if (USE_VN) {
                float4 v0 = __ldg(&vn4[(pj0 >> 17) * 32 + lane]);
                float4 v1 = __ldg(&vn4[(pj1 >> 17) * 32 + lane]);
                float4 v2 = __ldg(&vn4[(pj2 >> 17) * 32 + lane]);
                float4 v3 = __ldg(&vn4[(pj3 >> 17) * 32 + lane]);
                h0.x += v0.x; h0.y += v0.y; h0.z += v0.z; h0.w += v0.w;
                h1.x += v1.x; h1.y += v1.y; h1.z += v1.z; h1.w += v1.w;
                h2.x += v2.x; h2.y += v2.y; h2.z += v2.z; h2.w += v2.w;
                h3.x += v3.x; h3.y += v3.y; h3.z += v3.z; h3.w += v3.w;
            }
            acc.x += fmaxf(fmaf(ax0, w0.x, fmaf(ay0, w1.x, h0.x + bb.x)), 0.f);
            acc.y += fmaxf(fmaf(ax0, w0.y, fmaf(ay0, w1.y, h0.y + bb.y)), 0.f);
            acc.z += fmaxf(fmaf(ax0, w0.z, fmaf(ay0, w1.z, h0.z + bb.z)), 0.f);
            acc.w += fmaxf(fmaf(ax0, w0.w, fmaf(ay0, w1.w, h0.w + bb.w)), 0.f);
            acc.x += fmaxf(fmaf(ax1, w0.x, fmaf(ay1, w1.x, h1.x + bb.x)), 0.f);
            acc.y += fmaxf(fmaf(ax1, w0.y, fmaf(ay1, w1.y, h1.y + bb.y)), 0.f);
            acc.z += fmaxf(fmaf(ax1, w0.z, fmaf(ay1, w1.z, h1.z + bb.z)), 0.f);
            acc.w += fmaxf(fmaf(ax1, w0.w, fmaf(ay1, w1.w, h1.w + bb.w)), 0.f);
            acc.x += fmaxf(fmaf(ax2, w0.x, fmaf(ay2, w1.x, h2.x + bb.x)), 0.f);
            acc.y += fmaxf(fmaf(ax2, w0.y, fmaf(ay2, w1.y, h2.y + bb.y)), 0.f);
            acc.z += fmaxf(fmaf(ax2, w0.z, fmaf(ay2, w1.z, h2.z + bb.z)), 0.f);
            acc.w += fmaxf(fmaf(ax2, w0.w, fmaf(ay2, w1.w, h2.w + bb.w)), 0.f);
            acc.x += fmaxf(fmaf(ax3, w0.x, fmaf(ay3, w1.x, h3.x + bb.x)), 0.f);
            acc.y += fmaxf(fmaf(ax3, w0.y, fmaf(ay3, w1.y, h3.y + bb.y)), 0.f);
            acc.z += fmaxf(fmaf(ax3, w0.z, fmaf(ay3, w1.z, h3.z + bb.z)), 0.f);
            acc.w += fmaxf(fmaf(ax3, w0.w, fmaf(ay3, w1.w, h3.w + bb.w)), 0.f);
        }
        for (; j < cnt; j++) {
            int pj = __shfl_sync(0xffffffffu, p, j);
            float axs = __shfl_sync(0xffffffffu, ax, j);
            float ays = __shfl_sync(0xffffffffu, ay, j);
            float4 h = unpackh4(__ldg(&h16[(pj & 0x1FFFF) * 32 + lane]));
            if (USE_VN) {
                float4 v = __ldg(&vn4[(pj >> 17) * 32 + lane]);
                h.x += v.x; h.y += v.y; h.z += v.z; h.w += v.w;
            }
            acc.x += fmaxf(fmaf(axs, w0.x, fmaf(ays, w1.x, h.x + bb.x)), 0.f);
            acc.y += fmaxf(fmaf(axs, w0.y, fmaf(ays, w1.y, h.y + bb.y)), 0.f);
            acc.z += fmaxf(fmaf(axs, w0.z, fmaf(ays, w1.z, h.z + bb.z)), 0.f);
            acc.w += fmaxf(fmaf(axs, w0.w, fmaf(ays, w1.w, h.w + bb.w)), 0.f);
        }
    }
    ((float4*)g_aggr)[n * 32 + lane] = acc;
}

// ================= fused node MLP via 3xBF16 tensor-core MMA (m16n8k16) ============
#define UA_STRIDE 68    // uint32 words per A-pair row
#define USH_OFF 0
#define USL_OFF (64 * UA_STRIDE)
#define WPH_OFF (2 * 64 * UA_STRIDE)
#define WPL_OFF (WPH_OFF + 64 * WB_STRIDE)
#define SMEM_MMA_WORDS (WPL_OFF + 64 * WB_STRIDE)
#define SMEM_MMA_BYTES (SMEM_MMA_WORDS * 4)     // 104448 B -> 2 CTA/SM

__device__ __forceinline__ void stage_w(uint32_t* wph, uint32_t* wpl, int mat, int tid) {
    const uint4* srch = (const uint4*)(g_wpack + (mat * 2 + 0) * 8192);
    const uint4* srcl = (const uint4*)(g_wpack + (mat * 2 + 1) * 8192);
#pragma unroll
    for (int i = 0; i < 8; i++) {
        int f4 = i * 256 + tid;        // uint4 index 0..2047
        int kp = f4 >> 5;
        int n0 = (f4 & 31) * 4;
        *(uint4*)(wph + kp * WB_STRIDE + n0) = srch[f4];
        *(uint4*)(wpl + kp * WB_STRIDE + n0) = srcl[f4];
    }
}

__global__ void __launch_bounds__(256) k_layer_mma(
    const float* __restrict__ b1, const float* __restrict__ b2,
    const int* __restrict__ batch, int use_vn, int layer) {
    extern __shared__ uint32_t smw[];
    uint32_t* ush = smw + USH_OFF;
    uint32_t* usl = smw + USL_OFF;
    uint32_t* wph = smw + WPH_OFF;
    uint32_t* wpl = smw + WPL_OFF;
    int tid = threadIdx.x;
    int base = blockIdx.x * 64;
    int w = tid >> 5, lane = tid & 31;
    int gid = lane >> 2, tig = lane & 3;
    int mbase = (w & 3) * 16, nbase = (w >> 2) * 64;

    // ---- stage u = h + aggr (+ vn[batch]) as hi/lo bf16 pairs ----
    const float4* h4 = (const float4*)g_h;
    const float4* a4 = (const float4*)g_aggr;
    const float4* vn4 = (const float4*)g_vn;
#pragma unroll
    for (int i = 0; i < 8; i++) {
        int idx = i * 256 + tid;       // float4 index within 64x32
        int n = idx >> 5, c4 = idx & 31;
        float4 v = make_float4(0.f, 0.f, 0.f, 0.f);
        if (base + n < N_NODES) {
            v = h4[base * 32 + idx];
            float4 v2 = a4[base * 32 + idx];
            v.x += v2.x; v.y += v2.y; v.z += v2.z; v.w += v2.w;
            if (use_vn) {
                float4 v3 = vn4[batch[base + n] * 32 + c4];
                v.x += v3.x; v.y += v3.y; v.z += v3.z; v.w += v3.w;
            }
        }
        float hx = bfr(v.x), hy = bfr(v.y), hz = bfr(v.z), hw = bfr(v.w);
        int p = n * UA_STRIDE + 2 * c4;
        ush[p]     = pack2(hx, hy);
        ush[p + 1] = pack2(hz, hw);
        usl[p]     = pack2(v.x - hx, v.y - hy);
        usl[p + 1] = pack2(v.z - hz, v.w - hw);
    }
    stage_w(wph, wpl, layer * 2 + 0, tid);
    __syncthreads();

    float c[8][4];
#pragma unroll
    for (int j = 0; j < 8; j++)
#pragma unroll
        for (int q = 0; q < 4; q++) c[j][q] = 0.f;

    // ---- phase 1: t = relu(u @ W1 + b1), 3xBF16 ----
#pragma unroll 2
    for (int k0 = 0; k0 < 8; k0++) {
        int kb = k0 * 8;
        uint32_t ah0 = ush[(mbase + gid) * UA_STRIDE + kb + tig];
        uint32_t ah1 = ush[(mbase + gid + 8) * UA_STRIDE + kb + tig];
        uint32_t ah2 = ush[(mbase + gid) * UA_STRIDE + kb + tig + 4];
        uint32_t ah3 = ush[(mbase + gid + 8) * UA_STRIDE + kb + tig + 4];
        uint32_t al0 = usl[(mbase + gid) * UA_STRIDE + kb + tig];
        uint32_t al1 = usl[(mbase + gid + 8) * UA_STRIDE + kb + tig];
        uint32_t al2 = usl[(mbase + gid) * UA_STRIDE + kb + tig + 4];
        uint32_t al3 = usl[(mbase + gid + 8) * UA_STRIDE + kb + tig + 4];
#pragma unroll
        for (int j = 0; j < 8; j++) {
            int col = nbase + 8 * j + gid;
            uint32_t bh0 = wph[(kb + tig) * WB_STRIDE + col];
            uint32_t bh1 = wph[(kb + tig + 4) * WB_STRIDE + col];
            uint32_t bl0 = wpl[(kb + tig) * WB_STRIDE + col];
            uint32_t bl1 = wpl[(kb + tig + 4) * WB_STRIDE + col];
            mma16(c[j], ah0, ah1, ah2, ah3, bh0, bh1);
            mma16(c[j], al0, al1, al2, al3, bh0, bh1);
            mma16(c[j], ah0, ah1, ah2, ah3, bl0, bl1);
        }
    }
    __syncthreads();

    // ---- t -> ush/usl (split), W2 -> wph/wpl ----
#pragma unroll
    for (int j = 0; j < 8; j++) {
        int col = nbase + 8 * j + 2 * tig;
        float2 bb = *(const float2*)(b1 + col);
        float t0x = fmaxf(c[j][0] + bb.x, 0.f);
        float t0y = fmaxf(c[j][1] + bb.y, 0.f);
        float t1x = fmaxf(c[j][2] + bb.x, 0.f);
        float t1y = fmaxf(c[j][3] + bb.y, 0.f);
        int p = (nbase >> 1) + 4 * j + tig;
        float h0 = bfr(t0x), h1 = bfr(t0y), h2 = bfr(t1x), h3 = bfr(t1y);
        ush[(mbase + gid) * UA_STRIDE + p]     = pack2(h0, h1);
        usl[(mbase + gid) * UA_STRIDE + p]     = pack2(t0x - h0, t0y - h1);
        ush[(mbase + gid + 8) * UA_STRIDE + p] = pack2(h2, h3);
        usl[(mbase + gid + 8) * UA_STRIDE + p] = pack2(t1x - h2, t1y - h3);
        c[j][0] = 0.f; c[j][1] = 0.f; c[j][2] = 0.f; c[j][3] = 0.f;
    }
    stage_w(wph, wpl, layer * 2 + 1, tid);
    __syncthreads();

    // ---- phase 2: z = t @ W2 + b2, 3xBF16 ----
#pragma unroll 2
    for (int k0 = 0; k0 < 8; k0++) {
        int kb = k0 * 8;
        uint32_t ah0 = ush[(mbase + gid) * UA_STRIDE + kb + tig];
        uint32_t ah1 = ush[(mbase + gid + 8) * UA_STRIDE + kb + tig];
        uint32_t ah2 = ush[(mbase + gid) * UA_STRIDE + kb + tig + 4];
        uint32_t ah3 = ush[(mbase + gid + 8) * UA_STRIDE + kb + tig + 4];
        uint32_t al0 = usl[(mbase + gid) * UA_STRIDE + kb + tig];
        uint32_t al1 = usl[(mbase + gid + 8) * UA_STRIDE + kb + tig];
        uint32_t al2 = usl[(mbase + gid) * UA_STRIDE + kb + tig + 4];
        uint32_t al3 = usl[(mbase + gid + 8) * UA_STRIDE + kb + tig + 4];
#pragma unroll
        for (int j = 0; j < 8; j++) {
            int col = nbase + 8 * j + gid;
            uint32_t bh0 = wph[(kb + tig) * WB_STRIDE + col];
            uint32_t bh1 = wph[(kb + tig + 4) * WB_STRIDE + col];
            uint32_t bl0 = wpl[(kb + tig) * WB_STRIDE + col];
            uint32_t bl1 = wpl[(kb + tig + 4) * WB_STRIDE + col];
            mma16(c[j], ah0, ah1, ah2, ah3, bh0, bh1);
            mma16(c[j], al0, al1, al2, al3, bh0, bh1);
            mma16(c[j], ah0, ah1, ah2, ah3, bl0, bl1);
        }
    }

    // ---- epilogue: z to g_aggr, BN partial sums into slot[layer] ----
    int r0 = base + mbase + gid;
    int r1 = r0 + 8;
    bool v0 = r0 < N_NODES, v1 = r1 < N_NODES;
    float s[16], q[16];
#pragma unroll
    for (int j = 0; j < 8; j++) {
        int col = nbase + 8 * j + 2 * tig;
        float2 bb = *(const float2*)(b2 + col);
        float z0 = c[j][0] + bb.x, z1 = c[j][1] + bb.y;
        float z2 = c[j][2] + bb.x, z3 = c[j][3] + bb.y;
        if (v0) *(float2*)(g_aggr + r0 * HID + col) = make_float2(z0, z1);
        if (v1) *(float2*)(g_aggr + r1 * HID + col) = make_float2(z2, z3);
        float s0 = (v0 ? z0 : 0.f) + (v1 ? z2 : 0.f);
        float s1 = (v0 ? z1 : 0.f) + (v1 ? z3 : 0.f);
        float q0 = (v0 ? z0 * z0 : 0.f) + (v1 ? z2 * z2 : 0.f);
        float q1 = (v0 ? z1 * z1 : 0.f) + (v1 ? z3 * z3 : 0.f);
        s[2 * j] = s0; s[2 * j + 1] = s1;
        q[2 * j] = q0; q[2 * j + 1] = q1;
    }
#pragma unroll
    for (int off = 16; off >= 4; off >>= 1) {
#pragma unroll
        for (int i = 0; i < 16; i++) {
            s[i] += __shfl_xor_sync(0xffffffffu, s[i], off);
            q[i] += __shfl_xor_sync(0xffffffffu, q[i], off);
        }
    }
    __syncthreads();
    float* red_s = (float*)smw;
    float* red_q = (float*)smw + 512;
    if (gid == 0) {
#pragma unroll
        for (int j = 0; j < 8; j++) {
            int cl = 8 * j + 2 * tig;
            red_s[w * 64 + cl] = s[2 * j];
            red_s[w * 64 + cl + 1] = s[2 * j + 1];
            red_q[w * 64 + cl] = q[2 * j];
            red_q[w * 64 + cl + 1] = q[2 * j + 1];
        }
    }
    __syncthreads();
    if (tid < HID) {
        int grp = tid >> 6, cl = tid & 63;
        float S = 0.f, Q = 0.f;
#pragma unroll
        for (int m = 0; m < 4; m++) {
            int ww = grp * 4 + m;
            S += red_s[ww * 64 + cl];
            Q += red_q[ww * 64 + cl];
        }
        atomicAdd(&g_bnsum[layer * HID + tid], (double)S);
        atomicAdd(&g_bnsq[layer * HID + tid], (double)Q);
    }
}

// ====== BN stats (in-block) + apply + relu + pooling with block pre-reduction ======
// writes both g_h (f32) and g_h16 (fp16 copy for the next gather)
__global__ void k_bnapply(const int* __restrict__ batch,
                          const float* __restrict__ bn_g,
                          const float* __restrict__ bn_b,
                          int layer, int last) {
    __shared__ float sc[HID], sh[HID];
    __shared__ float4 rbuf[256];
    int tid = threadIdx.x;
    if (tid < HID) {
        double mu = g_bnsum[layer * HID + tid] / (double)N_NODES;
        double var = g_bnsq[layer * HID + tid] / (double)N_NODES - mu * mu;
        if (var < 0.0) var = 0.0;
        float scale = bn_g[layer * HID + tid] * rsqrtf((float)var + 1e-5f);
        sc[tid] = scale;
        sh[tid] = bn_b[layer * HID + tid] - (float)mu * scale;
    }
    __syncthreads();
    int idx = blockIdx.x * 256 + tid;          // exactly N_NODES*32
    int node = idx >> 5, j = idx & 31;
    float4 z = ((const float4*)g_aggr)[idx];
    float4 s4 = ((const float4*)sc)[j];
    float4 h4 = ((const float4*)sh)[j];
    float4 h;
    h.x = fmaxf(z.x * s4.x + h4.x, 0.f);
    h.y = fmaxf(z.y * s4.y + h4.y, 0.f);
    h.z = fmaxf(z.z * s4.z + h4.z, 0.f);
    h.w = fmaxf(z.w * s4.w + h4.w, 0.f);
    ((float4*)g_h)[idx] = h;
    g_h16[idx] = make_uint2(packh2(h.x, h.y), packh2(h.z, h.w));

    int nfirst = blockIdx.x * 8;
    int g0 = batch[nfirst];
    int g7 = batch[nfirst + 7];
    float* target = last ? g_gsum : g_vnup;
    if (g0 == g7) {
        rbuf[tid] = h;
        __syncthreads();
        if (tid < 128) {
            float4 o = rbuf[tid + 128];
            rbuf[tid].x += o.x; rbuf[tid].y += o.y;
            rbuf[tid].z += o.z; rbuf[tid].w += o.w;
        }
        __syncthreads();
        if (tid < 64) {
            float4 o = rbuf[tid + 64];
            rbuf[tid].x += o.x; rbuf[tid].y += o.y;
            rbuf[tid].z += o.z; rbuf[tid].w += o.w;
        }
        __syncthreads();
        if (tid < 32) {
            float4 o = rbuf[tid + 32];
            float4 r = rbuf[tid];
            r.x += o.x; r.y += o.y; r.z += o.z; r.w += o.w;
            red_add_v4(target + g0 * HID + tid * 4, r);
        }
        if (last && tid == 0) atomicAdd(&g_gcnt[g0], 8);
    } else {
        int g = batch[node];
        red_add_v4(target + g * HID + j * 4, h);
        if (last && j == 0) atomicAdd(&g_gcnt[g], 1);
    }
}

// ================= virtual-node MLP =================
__global__ void k_vn(const float* __restrict__ W1, const float* __restrict__ b1,
                     const float* __restrict__ W2, const float* __restrict__ b2) {
    __shared__ float up[HID];
    __shared__ float t[HID];
    int g = blockIdx.x, j = threadIdx.x;
    up[j] = g_vnup[g * HID + j];
    g_vnup[g * HID + j] = 0.f;
    __syncthreads();
    float s = b1[j];
    for (int k = 0; k < HID; k++) s += up[k] * W1[k * HID + j];
    t[j] = fmaxf(s, 0.f);
    __syncthreads();
    float s2 = b2[j];
    for (int k = 0; k < HID; k++) s2 += t[k] * W2[k * HID + j];
    g_vn[g * HID + j] += s2;
}

// ============ classifier head (also restores g_deg = 0 for the next call) ==========
__global__ void k_cls(const float* __restrict__ W1, const float* __restrict__ b1,
                      const float* __restrict__ W2, const float* __restrict__ b2,
                      float* __restrict__ out) {
    __shared__ float gv[HID];
    __shared__ float t[HID];
    __shared__ float red[HID];
    int g = blockIdx.x, j = threadIdx.x;
    for (int i = g * HID + j; i < N_NODES; i += NUM_GRAPHS * HID) g_deg[i] = 0;
    float inv = 1.f / fmaxf((float)g_gcnt[g], 1.f);
    gv[j] = g_gsum[g * HID + j] * inv;
    __syncthreads();
    float s = b1[j];
    for (int k = 0; k < HID; k++) s += gv[k] * W1[k * HID + j];
    t[j] = fmaxf(s, 0.f);
    __syncthreads();
    red[j] = t[j] * W2[j];
    __syncthreads();
    for (int off = 64; off > 0; off >>= 1) {
        if (j < off) red[j] += red[j + off];
        __syncthreads();
    }
    if (j == 0) out[g] = red[0] + b2[0];
}

// ================= host launcher =================
extern "C" void kernel_launch(void* const* d_in, const int* in_sizes, int n_in,
                              void* d_out, int out_size) {
    const float* x    = (const float*)d_in[0];
    const float* ea   = (const float*)d_in[1];
    const int*   ei   = (const int*)d_in[2];
    const int*   batch= (const int*)d_in[3];
    const float* W_in = (const float*)d_in[4];
    const float* b_in = (const float*)d_in[5];
    const float* W_e  = (const float*)d_in[6];
    const float* b_e  = (const float*)d_in[7];
    const float* cW1  = (const float*)d_in[8];
    const float* cb1  = (const float*)d_in[9];
    const float* cW2  = (const float*)d_in[10];
    const float* cb2  = (const float*)d_in[11];
    const float* bng  = (const float*)d_in[12];
    const float* bnb  = (const float*)d_in[13];
    const float* vW1  = (const float*)d_in[14];
    const float* vb1  = (const float*)d_in[15];
    const float* vW2  = (const float*)d_in[16];
    const float* vb2  = (const float*)d_in[17];
    const float* clW1 = (const float*)d_in[18];
    const float* clb1 = (const float*)d_in[19];
    const float* clW2 = (const float*)d_in[20];
    const float* clb2 = (const float*)d_in[21];
    float* out = (float*)d_out;

    cudaFuncSetAttribute(k_layer_mma, cudaFuncAttributeMaxDynamicSharedMemorySize,
                         SMEM_MMA_BYTES);
    cudaFuncSetAttribute(k_input_mma, cudaFuncAttributeMaxDynamicSharedMemorySize,
                         SMEM_IN_BYTES);

    const int NODE_BLOCKS = (N_NODES + 63) / 64;      // 782
    const int ELEM_BLOCKS = (N_NODES * 32) / 256;     // 6250 (exact)
    const int WARP_BLOCKS = (N_NODES + 7) / 8;        // 6250 (warp per node)
    const int EDGE_BLOCKS = N_EDGES / 256;            // 3125 (exact)
    const int SC_BLOCKS = (N_EDGES + 511) / 512;      // 1563

    k_wprep<<<9, 256>>>(cW1, cW2, W_in);
    k_hist<<<EDGE_BLOCKS, 256>>>(ei);
    k_scan<<<1, 1024>>>();
    k_scatter<<<SC_BLOCKS, 256>>>(ei, ea, batch);

    k_input_mma<<<NODE_BLOCKS, 256, SMEM_IN_BYTES>>>(x, b_in);
    for (int L = 0; L < NUM_LAYERS; L++) {
        if (L == 0) k_gather<0><<<WARP_BLOCKS, 256>>>(W_e, b_e);
        else        k_gather<1><<<WARP_BLOCKS, 256>>>(W_e, b_e);
        k_layer_mma<<<NODE_BLOCKS, 256, SMEM_MMA_BYTES>>>(
            cb1 + L * HID, cb2 + L * HID, batch, (L > 0) ? 1 : 0, L);
        k_bnapply<<<ELEM_BLOCKS, 256>>>(batch, bng, bnb, L,
                                        (L == NUM_LAYERS - 1) ? 1 : 0);
        if (L != NUM_LAYERS - 1) k_vn<<<NUM_GRAPHS, HID>>>(vW1, vb1, vW2, vb2);
    }
    k_cls<<<NUM_GRAPHS, HID>>>(clW1, clb1, clW2, clb2, out);
}

// round 17
// speedup vs baseline: 1.0388x; 1.0388x over previous
#include <cuda_runtime.h>
#include <cuda_bf16.h>
#include <cstdint>

#define N_NODES 50000
#define N_EDGES 800000
#define IN_DIM 64
#define HID 128
#define NUM_LAYERS 4
#define NUM_GRAPHS 128

// ---------------- scratch (device globals; no allocation allowed) ----------------
__device__ __align__(16) float g_h[N_NODES * HID];     // node features
__device__ __align__(16) float g_aggr[N_NODES * HID];  // edge aggregation; reused as z
__device__ __align__(16) float g_vn[NUM_GRAPHS * HID];
__device__ __align__(16) float g_vnup[NUM_GRAPHS * HID];
__device__ double g_bnsum[NUM_LAYERS * HID];           // per-layer slots, zeroed in k_input
__device__ double g_bnsq[NUM_LAYERS * HID];
__device__ __align__(16) float g_gsum[NUM_GRAPHS * HID];
__device__ int g_gcnt[NUM_GRAPHS];
// CSR (by destination) built once per call.
// g_deg: starts all-zero (static init on call 1; re-zeroed by k_cls at end of each call)
__device__ int g_deg[N_NODES];
__device__ int g_rowptr[N_NODES + 1];
__device__ __align__(16) int4 g_edge[N_EDGES];  // {src|batch<<17, ax_bits, ay_bits, 0}
// pre-packed bf16 hi/lo weights: [mat 0..8][part 0..1][8192]  (mat 8 = W_in, 4096 used)
__device__ __align__(16) uint32_t g_wpack[9 * 2 * 8192];

__device__ __forceinline__ void red_add_v4(float* addr, float4 v) {
    asm volatile("red.global.add.v4.f32 [%0], {%1,%2,%3,%4};"
                 :: "l"(addr), "f"(v.x), "f"(v.y), "f"(v.z), "f"(v.w) : "memory");
}

// pack two f32 -> bf16x2 (e0 -> low half / smaller k, e1 -> high half)
__device__ __forceinline__ uint32_t pack2(float e0, float e1) {
    uint32_t r;
    asm("cvt.rn.bf16x2.f32 %0, %1, %2;" : "=r"(r) : "f"(e1), "f"(e0));
    return r;
}
// bf16 round-trip (keeps hi part as f32)
__device__ __forceinline__ float bfr(float x) {
    return __bfloat162float(__float2bfloat16_rn(x));
}

__device__ __forceinline__ void mma16(float* c, uint32_t a0, uint32_t a1, uint32_t a2,
                                      uint32_t a3, uint32_t b0, uint32_t b1) {
    asm volatile(
        "mma.sync.aligned.m16n8k16.row.col.f32.bf16.bf16.f32 "
        "{%0,%1,%2,%3}, {%4,%5,%6,%7}, {%8,%9}, {%0,%1,%2,%3};\n"
        : "+f"(c[0]), "+f"(c[1]), "+f"(c[2]), "+f"(c[3])
        : "r"(a0), "r"(a1), "r"(a2), "r"(a3), "r"(b0), "r"(b1));
}

// ================= weight pre-pack: 8 layer mats + W_in -> bf16 hi/lo pairs ========
__global__ void k_wprep(const float* __restrict__ cW1, const float* __restrict__ cW2,
                        const float* __restrict__ Win) {
    int mat = blockIdx.x;              // 0..7: layer*2+(0=W1,1=W2); 8: W_in
    int tid = threadIdx.x;
    if (mat < 8) {
        int L = mat >> 1;
        const float* W = (mat & 1) ? (cW2 + L * HID * HID) : (cW1 + L * HID * HID);
        uint32_t* dsth = g_wpack + (mat * 2 + 0) * 8192;
        uint32_t* dstl = g_wpack + (mat * 2 + 1) * 8192;
#pragma unroll
        for (int i = 0; i < 32; i++) {
            int flat = i * 256 + tid;      // 0..8191 = kp*128 + n
            int kp = flat >> 7, n = flat & 127;
            float w0 = W[(2 * kp) * HID + n];
            float w1 = W[(2 * kp + 1) * HID + n];
            float h0 = bfr(w0), h1 = bfr(w1);
            dsth[flat] = pack2(h0, h1);
            dstl[flat] = pack2(w0 - h0, w1 - h1);
        }
    } else {
        // W_in: [64][128] -> 32 kp x 128
        uint32_t* dsth = g_wpack + (8 * 2 + 0) * 8192;
        uint32_t* dstl = g_wpack + (8 * 2 + 1) * 8192;
#pragma unroll
        for (int i = 0; i < 16; i++) {
            int flat = i * 256 + tid;      // 0..4095 = kp*128 + n
            int kp = flat >> 7, n = flat & 127;
            float w0 = Win[(2 * kp) * HID + n];
            float w1 = Win[(2 * kp + 1) * HID + n];
            float h0 = bfr(w0), h1 = bfr(w1);
            dsth[flat] = pack2(h0, h1);
            dstl[flat] = pack2(w0 - h0, w1 - h1);
        }
    }
}

// ================= CSR build =================
__global__ void k_hist(const int* __restrict__ ei) {
    int e = blockIdx.x * 256 + threadIdx.x;   // grid exactly N_EDGES/256
    atomicAdd(&g_deg[ei[N_EDGES + e]], 1);
}

__global__ void k_scan() {
    __shared__ int sums[1024];
    int tid = threadIdx.x;
    const int CH = (N_NODES + 1023) / 1024;   // 49
    int st = tid * CH;
    int en = st + CH; if (en > N_NODES) en = N_NODES;
    int s = 0;
    for (int i = st; i < en; i++) s += g_deg[i];
    sums[tid] = s;
    __syncthreads();
    for (int off = 1; off < 1024; off <<= 1) {
        int v = (tid >= off) ? sums[tid - off] : 0;
        __syncthreads();
        sums[tid] += v;
        __syncthreads();
    }
    int run = sums[tid] - s;
    for (int i = st; i < en; i++) {
        int c = g_deg[i];
        g_rowptr[i] = run;
        g_deg[i] = run;     // cursor for scatter
        run += c;
    }
    if (tid == 1023) g_rowptr[N_NODES] = N_EDGES;
}

__global__ void k_scatter(const int* __restrict__ ei, const float* __restrict__ ea,
                          const int* __restrict__ batch) {
    int e = blockIdx.x * 256 + threadIdx.x;   // grid exactly N_EDGES/256
    int d = ei[N_EDGES + e];
    int s = ei[e];
    float2 a = ((const float2*)ea)[e];
    int pos = atomicAdd(&g_deg[d], 1);
    g_edge[pos] = make_int4(s | (batch[s] << 17),
                            __float_as_int(a.x), __float_as_int(a.y), 0);
}

// ======== input projection via 3xBF16 MMA: h = x @ W_in + b_in (+ aux init) ========
#define UA2_STRIDE 36   // uint32 words per x-pair row (64 feats = 32 pairs + pad)
#define WB_STRIDE 136   // uint32 words per W-kpair row
#define USH2_OFF 0
#define USL2_OFF (64 * UA2_STRIDE)
#define WPH2_OFF (2 * 64 * UA2_STRIDE)
#define WPL2_OFF (WPH2_OFF + 32 * WB_STRIDE)
#define SMEM_IN_WORDS (WPL2_OFF + 32 * WB_STRIDE)
#define SMEM_IN_BYTES (SMEM_IN_WORDS * 4)      // 53248 B

__global__ void __launch_bounds__(256) k_input_mma(const float* __restrict__ x,
                                                   const float* __restrict__ bin) {
    extern __shared__ uint32_t smw[];
    uint32_t* ush = smw + USH2_OFF;
    uint32_t* usl = smw + USL2_OFF;
    uint32_t* wph = smw + WPH2_OFF;
    uint32_t* wpl = smw + WPL2_OFF;
    int tid = threadIdx.x;
    int base = blockIdx.x * 64;
    int w = tid >> 5, lane = tid & 31;
    int gid = lane >> 2, tig = lane & 3;
    int mbase = (w & 3) * 16, nbase = (w >> 2) * 64;

    // aux init (block 0 only; independent buffers)
    if (blockIdx.x == 0) {
        for (int i = tid; i < NUM_GRAPHS * HID; i += 256) {
            g_vn[i] = 0.f; g_vnup[i] = 0.f; g_gsum[i] = 0.f;
        }
        if (tid < HID) {
#pragma unroll
            for (int l = 0; l < NUM_LAYERS; l++) {
                g_bnsum[l * HID + tid] = 0.0;
                g_bnsq[l * HID + tid] = 0.0;
            }
        }
        if (tid < NUM_GRAPHS) g_gcnt[tid] = 0;
    }

    // stage x (64 nodes x 64 feats) as hi/lo bf16 pairs
    const float4* x4 = (const float4*)x;
#pragma unroll
    for (int i = 0; i < 4; i++) {
        int idx = i * 256 + tid;       // float4 index within 64x16
        int n = idx >> 4, c4 = idx & 15;
        float4 v = make_float4(0.f, 0.f, 0.f, 0.f);
        if (base + n < N_NODES) v = x4[(base + n) * 16 + c4];
        float hx = bfr(v.x), hy = bfr(v.y), hz = bfr(v.z), hw = bfr(v.w);
        int p = n * UA2_STRIDE + 2 * c4;
        ush[p]     = pack2(hx, hy);
        ush[p + 1] = pack2(hz, hw);
        usl[p]     = pack2(v.x - hx, v.y - hy);
        usl[p + 1] = pack2(v.z - hz, v.w - hw);
    }
    // stage pre-packed W_in (32 kp x 128)
    {
        const uint4* srch = (const uint4*)(g_wpack + (8 * 2 + 0) * 8192);
        const uint4* srcl = (const uint4*)(g_wpack + (8 * 2 + 1) * 8192);
#pragma unroll
        for (int i = 0; i < 4; i++) {
            int f4 = i * 256 + tid;        // uint4 index 0..1023
            int kp = f4 >> 5;
            int n0 = (f4 & 31) * 4;
            *(uint4*)(wph + kp * WB_STRIDE + n0) = srch[f4];
            *(uint4*)(wpl + kp * WB_STRIDE + n0) = srcl[f4];
        }
    }
    __syncthreads();

    float c[8][4];
#pragma unroll
    for (int j = 0; j < 8; j++)
#pragma unroll
        for (int q = 0; q < 4; q++) c[j][q] = 0.f;

#pragma unroll
    for (int k0 = 0; k0 < 4; k0++) {
        int kb = k0 * 8;
        uint32_t ah0 = ush[(mbase + gid) * UA2_STRIDE + kb + tig];
        uint32_t ah1 = ush[(mbase + gid + 8) * UA2_STRIDE + kb + tig];
        uint32_t ah2 = ush[(mbase + gid) * UA2_STRIDE + kb + tig + 4];
        uint32_t ah3 = ush[(mbase + gid + 8) * UA2_STRIDE + kb + tig + 4];
        uint32_t al0 = usl[(mbase + gid) * UA2_STRIDE + kb + tig];
        uint32_t al1 = usl[(mbase + gid + 8) * UA2_STRIDE + kb + tig];
        uint32_t al2 = usl[(mbase + gid) * UA2_STRIDE + kb + tig + 4];
        uint32_t al3 = usl[(mbase + gid + 8) * UA2_STRIDE + kb + tig + 4];
#pragma unroll
        for (int j = 0; j < 8; j++) {
            int col = nbase + 8 * j + gid;
            uint32_t bh0 = wph[(kb + tig) * WB_STRIDE + col];
            uint32_t bh1 = wph[(kb + tig + 4) * WB_STRIDE + col];
            uint32_t bl0 = wpl[(kb + tig) * WB_STRIDE + col];
            uint32_t bl1 = wpl[(kb + tig + 4) * WB_STRIDE + col];
            mma16(c[j], ah0, ah1, ah2, ah3, bh0, bh1);
            mma16(c[j], al0, al1, al2, al3, bh0, bh1);
            mma16(c[j], ah0, ah1, ah2, ah3, bl0, bl1);
        }
    }

    int r0 = base + mbase + gid;
    int r1 = r0 + 8;
    bool v0 = r0 < N_NODES, v1 = r1 < N_NODES;
#pragma unroll
    for (int j = 0; j < 8; j++) {
        int col = nbase + 8 * j + 2 * tig;
        float2 bb = *(const float2*)(bin + col);
        if (v0) *(float2*)(g_h + r0 * HID + col) =
            make_float2(c[j][0] + bb.x, c[j][1] + bb.y);
        if (v1) *(float2*)(g_h + r1 * HID + col) =
            make_float2(c[j][2] + bb.x, c[j][3] + bb.y);
    }
}

// ================= edge gather: aggr[n] = sum relu(h[src]+vn[b[src]]+e) ============
// one warp per node, CSR lists; int4 edge records; 4-way edge unroll for MLP=4.
template <int USE_VN>
__global__ void __launch_bounds__(256) k_gather(const float* __restrict__ We,
                                                const float* __restrict__ be) {
    int lane = threadIdx.x & 31;
    int n = (blockIdx.x * 256 + threadIdx.x) >> 5;   // grid exactly N_NODES warps
    float4 w0 = ((const float4*)We)[lane];
    float4 w1 = ((const float4*)(We + HID))[lane];
    float4 bb = ((const float4*)be)[lane];
    int start = g_rowptr[n];
    int end = g_rowptr[n + 1];
    float4 acc = make_float4(0.f, 0.f, 0.f, 0.f);
    const float4* h4 = (const float4*)g_h;
    const float4* vn4 = (const float4*)g_vn;
    for (int base = start; base < end; base += 32) {
        int idx = base + lane;
        int p = 0;
        float ax = 0.f, ay = 0.f;
        if (idx < end) {
            int4 ev = __ldg(&g_edge[idx]);
            p = ev.x; ax = __int_as_float(ev.y); ay = __int_as_float(ev.z);
        }
        int cnt = end - base; if (cnt > 32) cnt = 32;
        int j = 0;
        for (; j + 3 < cnt; j += 4) {
            int pj0 = __shfl_sync(0xffffffffu, p, j);
            float ax0 = __shfl_sync(0xffffffffu, ax, j);
            float ay0 = __shfl_sync(0xffffffffu, ay, j);
            int pj1 = __shfl_sync(0xffffffffu, p, j + 1);
            float ax1 = __shfl_sync(0xffffffffu, ax, j + 1);
            float ay1 = __shfl_sync(0xffffffffu, ay, j + 1);
            int pj2 = __shfl_sync(0xffffffffu, p, j + 2);
            float ax2 = __shfl_sync(0xffffffffu, ax, j + 2);
            float ay2 = __shfl_sync(0xffffffffu, ay, j + 2);
            int pj3 = __shfl_sync(0xffffffffu, p, j + 3);
            float ax3 = __shfl_sync(0xffffffffu, ax, j + 3);
            float ay3 = __shfl_sync(0xffffffffu, ay, j + 3);
            float4 h0 = __ldg(&h4[(pj0 & 0x1FFFF) * 32 + lane]);
            float4 h1 = __ldg(&h4[(pj1 & 0x1FFFF) * 32 + lane]);
            float4 h2 = __ldg(&h4[(pj2 & 0x1FFFF) * 32 + lane]);
            float4 h3 = __ldg(&h4[(pj3 & 0x1FFFF) * 32 + lane]);
            if (USE_VN) {
                float4 v0 = __ldg(&vn4[(pj0 >> 17) * 32 + lane]);
                float4 v1 = __ldg(&vn4[(pj1 >> 17) * 32 + lane]);
                float4 v2 = __ldg(&vn4[(pj2 >> 17) * 32 + lane]);
                float4 v3 = __ldg(&vn4[(pj3 >> 17) * 32 + lane]);
                h0.x += v0.x; h0.y += v0.y; h0.z += v0.z; h0.w += v0.w;
                h1.x += v1.x; h1.y += v1.y; h1.z += v1.z; h1.w += v1.w;
                h2.x += v2.x; h2.y += v2.y; h2.z += v2.z; h2.w += v2.w;
                h3.x += v3.x; h3.y += v3.y; h3.z += v3.z; h3.w += v3.w;
            }
            acc.x += fmaxf(fmaf(ax0, w0.x, fmaf(ay0, w1.x, h0.x + bb.x)), 0.f);
            acc.y += fmaxf(fmaf(ax0, w0.y, fmaf(ay0, w1.y, h0.y + bb.y)), 0.f);
            acc.z += fmaxf(fmaf(ax0, w0.z, fmaf(ay0, w1.z, h0.z + bb.z)), 0.f);
            acc.w += fmaxf(fmaf(ax0, w0.w, fmaf(ay0, w1.w, h0.w + bb.w)), 0.f);
            acc.x += fmaxf(fmaf(ax1, w0.x, fmaf(ay1, w1.x, h1.x + bb.x)), 0.f);
            acc.y += fmaxf(fmaf(ax1, w0.y, fmaf(ay1, w1.y, h1.y + bb.y)), 0.f);
            acc.z += fmaxf(fmaf(ax1, w0.z, fmaf(ay1, w1.z, h1.z + bb.z)), 0.f);
            acc.w += fmaxf(fmaf(ax1, w0.w, fmaf(ay1, w1.w, h1.w + bb.w)), 0.f);
            acc.x += fmaxf(fmaf(ax2, w0.x, fmaf(ay2, w1.x, h2.x + bb.x)), 0.f);
            acc.y += fmaxf(fmaf(ax2, w0.y, fmaf(ay2, w1.y, h2.y + bb.y)), 0.f);
            acc.z += fmaxf(fmaf(ax2, w0.z, fmaf(ay2, w1.z, h2.z + bb.z)), 0.f);
            acc.w += fmaxf(fmaf(ax2, w0.w, fmaf(ay2, w1.w, h2.w + bb.w)), 0.f);
            acc.x += fmaxf(fmaf(ax3, w0.x, fmaf(ay3, w1.x, h3.x + bb.x)), 0.f);
            acc.y += fmaxf(fmaf(ax3, w0.y, fmaf(ay3, w1.y, h3.y + bb.y)), 0.f);
            acc.z += fmaxf(fmaf(ax3, w0.z, fmaf(ay3, w1.z, h3.z + bb.z)), 0.f);
            acc.w += fmaxf(fmaf(ax3, w0.w, fmaf(ay3, w1.w, h3.w + bb.w)), 0.f);
        }
        for (; j < cnt; j++) {
            int pj = __shfl_sync(0xffffffffu, p, j);
            float axs = __shfl_sync(0xffffffffu, ax, j);
            float ays = __shfl_sync(0xffffffffu, ay, j);
            float4 h = __ldg(&h4[(pj & 0x1FFFF) * 32 + lane]);
            if (USE_VN) {
                float4 v = __ldg(&vn4[(pj >> 17) * 32 + lane]);
                h.x += v.x; h.y += v.y; h.z += v.z; h.w += v.w;
            }
            acc.x += fmaxf(fmaf(axs, w0.x, fmaf(ays, w1.x, h.x + bb.x)), 0.f);
            acc.y += fmaxf(fmaf(axs, w0.y, fmaf(ays, w1.y, h.y + bb.y)), 0.f);
            acc.z += fmaxf(fmaf(axs, w0.z, fmaf(ays, w1.z, h.z + bb.z)), 0.f);
            acc.w += fmaxf(fmaf(axs, w0.w, fmaf(ays, w1.w, h.w + bb.w)), 0.f);
        }
    }
    ((float4*)g_aggr)[n * 32 + lane] = acc;
}

// ================= fused node MLP via 3xBF16 tensor-core MMA (m16n8k16) ============
#define UA_STRIDE 68    // uint32 words per A-pair row
#define USH_OFF 0
#define USL_OFF (64 * UA_STRIDE)
#define WPH_OFF (2 * 64 * UA_STRIDE)
#define WPL_OFF (WPH_OFF + 64 * WB_STRIDE)
#define SMEM_MMA_WORDS (WPL_OFF + 64 * WB_STRIDE)
#define SMEM_MMA_BYTES (SMEM_MMA_WORDS * 4)     // 104448 B -> 2 CTA/SM

// stage pre-packed weights (matrix index mat) into strided smem
__device__ __forceinline__ void stage_w(uint32_t* wph, uint32_t* wpl, int mat, int tid) {
    const uint4* srch = (const uint4*)(g_wpack + (mat * 2 + 0) * 8192);
    const uint4* srcl = (const uint4*)(g_wpack + (mat * 2 + 1) * 8192);
#pragma unroll
    for (int i = 0; i < 8; i++) {
        int f4 = i * 256 + tid;        // uint4 index 0..2047
        int kp = f4 >> 5;
        int n0 = (f4 & 31) * 4;
        *(uint4*)(wph + kp * WB_STRIDE + n0) = srch[f4];
        *(uint4*)(wpl + kp * WB_STRIDE + n0) = srcl[f4];
    }
}

__global__ void __launch_bounds__(256) k_layer_mma(
    const float* __restrict__ b1, const float* __restrict__ b2,
    const int* __restrict__ batch, int use_vn, int layer) {
    extern __shared__ uint32_t smw[];
    uint32_t* ush = smw + USH_OFF;
    uint32_t* usl = smw + USL_OFF;
    uint32_t* wph = smw + WPH_OFF;
    uint32_t* wpl = smw + WPL_OFF;
    int tid = threadIdx.x;
    int base = blockIdx.x * 64;
    int w = tid >> 5, lane = tid & 31;
    int gid = lane >> 2, tig = lane & 3;
    int mbase = (w & 3) * 16, nbase = (w >> 2) * 64;

    // ---- stage u = h + aggr (+ vn[batch]) as hi/lo bf16 pairs ----
    const float4* h4 = (const float4*)g_h;
    const float4* a4 = (const float4*)g_aggr;
    const float4* vn4 = (const float4*)g_vn;
#pragma unroll
    for (int i = 0; i < 8; i++) {
        int idx = i * 256 + tid;       // float4 index within 64x32
        int n = idx >> 5, c4 = idx & 31;
        float4 v = make_float4(0.f, 0.f, 0.f, 0.f);
        if (base + n < N_NODES) {
            v = h4[base * 32 + idx];
            float4 v2 = a4[base * 32 + idx];
            v.x += v2.x; v.y += v2.y; v.z += v2.z; v.w += v2.w;
            if (use_vn) {
                float4 v3 = vn4[batch[base + n] * 32 + c4];
                v.x += v3.x; v.y += v3.y; v.z += v3.z; v.w += v3.w;
            }
        }
        float hx = bfr(v.x), hy = bfr(v.y), hz = bfr(v.z), hw = bfr(v.w);
        int p = n * UA_STRIDE + 2 * c4;
        ush[p]     = pack2(hx, hy);
        ush[p + 1] = pack2(hz, hw);
        usl[p]     = pack2(v.x - hx, v.y - hy);
        usl[p + 1] = pack2(v.z - hz, v.w - hw);
    }
    stage_w(wph, wpl, layer * 2 + 0, tid);
    __syncthreads();

    float c[8][4];
#pragma unroll
    for (int j = 0; j < 8; j++)
#pragma unroll
        for (int q = 0; q < 4; q++) c[j][q] = 0.f;

    // ---- phase 1: t = relu(u @ W1 + b1), 3xBF16 ----
#pragma unroll 2
    for (int k0 = 0; k0 < 8; k0++) {
        int kb = k0 * 8;
        uint32_t ah0 = ush[(mbase + gid) * UA_STRIDE + kb + tig];
        uint32_t ah1 = ush[(mbase + gid + 8) * UA_STRIDE + kb + tig];
        uint32_t ah2 = ush[(mbase + gid) * UA_STRIDE + kb + tig + 4];
        uint32_t ah3 = ush[(mbase + gid + 8) * UA_STRIDE + kb + tig + 4];
        uint32_t al0 = usl[(mbase + gid) * UA_STRIDE + kb + tig];
        uint32_t al1 = usl[(mbase + gid + 8) * UA_STRIDE + kb + tig];
        uint32_t al2 = usl[(mbase + gid) * UA_STRIDE + kb + tig + 4];
        uint32_t al3 = usl[(mbase + gid + 8) * UA_STRIDE + kb + tig + 4];
#pragma unroll
        for (int j = 0; j < 8; j++) {
            int col = nbase + 8 * j + gid;
            uint32_t bh0 = wph[(kb + tig) * WB_STRIDE + col];
            uint32_t bh1 = wph[(kb + tig + 4) * WB_STRIDE + col];
            uint32_t bl0 = wpl[(kb + tig) * WB_STRIDE + col];
            uint32_t bl1 = wpl[(kb + tig + 4) * WB_STRIDE + col];
            mma16(c[j], ah0, ah1, ah2, ah3, bh0, bh1);
            mma16(c[j], al0, al1, al2, al3, bh0, bh1);
            mma16(c[j], ah0, ah1, ah2, ah3, bl0, bl1);
        }
    }
    __syncthreads();

    // ---- t -> ush/usl (split), W2 -> wph/wpl ----
#pragma unroll
    for (int j = 0; j < 8; j++) {
        int col = nbase + 8 * j + 2 * tig;
        float2 bb = *(const float2*)(b1 + col);
        float t0x = fmaxf(c[j][0] + bb.x, 0.f);
        float t0y = fmaxf(c[j][1] + bb.y, 0.f);
        float t1x = fmaxf(c[j][2] + bb.x, 0.f);
        float t1y = fmaxf(c[j][3] + bb.y, 0.f);
        int p = (nbase >> 1) + 4 * j + tig;
        float h0 = bfr(t0x), h1 = bfr(t0y), h2 = bfr(t1x), h3 = bfr(t1y);
        ush[(mbase + gid) * UA_STRIDE + p]     = pack2(h0, h1);
        usl[(mbase + gid) * UA_STRIDE + p]     = pack2(t0x - h0, t0y - h1);
        ush[(mbase + gid + 8) * UA_STRIDE + p] = pack2(h2, h3);
        usl[(mbase + gid + 8) * UA_STRIDE + p] = pack2(t1x - h2, t1y - h3);
        c[j][0] = 0.f; c[j][1] = 0.f; c[j][2] = 0.f; c[j][3] = 0.f;
    }
    stage_w(wph, wpl, layer * 2 + 1, tid);
    __syncthreads();

    // ---- phase 2: z = t @ W2 + b2, 3xBF16 ----
#pragma unroll 2
    for (int k0 = 0; k0 < 8; k0++) {
        int kb = k0 * 8;
        uint32_t ah0 = ush[(mbase + gid) * UA_STRIDE + kb + tig];
        uint32_t ah1 = ush[(mbase + gid + 8) * UA_STRIDE + kb + tig];
        uint32_t ah2 = ush[(mbase + gid) * UA_STRIDE + kb + tig + 4];
        uint32_t ah3 = ush[(mbase + gid + 8) * UA_STRIDE + kb + tig + 4];
        uint32_t al0 = usl[(mbase + gid) * UA_STRIDE + kb + tig];
        uint32_t al1 = usl[(mbase + gid + 8) * UA_STRIDE + kb + tig];
        uint32_t al2 = usl[(mbase + gid) * UA_STRIDE + kb + tig + 4];
        uint32_t al3 = usl[(mbase + gid + 8) * UA_STRIDE + kb + tig + 4];
#pragma unroll
        for (int j = 0; j < 8; j++) {
            int col = nbase + 8 * j + gid;
            uint32_t bh0 = wph[(kb + tig) * WB_STRIDE + col];
            uint32_t bh1 = wph[(kb + tig + 4) * WB_STRIDE + col];
            uint32_t bl0 = wpl[(kb + tig) * WB_STRIDE + col];
            uint32_t bl1 = wpl[(kb + tig + 4) * WB_STRIDE + col];
            mma16(c[j], ah0, ah1, ah2, ah3, bh0, bh1);
            mma16(c[j], al0, al1, al2, al3, bh0, bh1);
            mma16(c[j], ah0, ah1, ah2, ah3, bl0, bl1);
        }
    }

    // ---- epilogue: z to g_aggr, BN partial sums into slot[layer] ----
    int r0 = base + mbase + gid;
    int r1 = r0 + 8;
    bool v0 = r0 < N_NODES, v1 = r1 < N_NODES;
    float s[16], q[16];
#pragma unroll
    for (int j = 0; j < 8; j++) {
        int col = nbase + 8 * j + 2 * tig;
        float2 bb = *(const float2*)(b2 + col);
        float z0 = c[j][0] + bb.x, z1 = c[j][1] + bb.y;
        float z2 = c[j][2] + bb.x, z3 = c[j][3] + bb.y;
        if (v0) *(float2*)(g_aggr + r0 * HID + col) = make_float2(z0, z1);
        if (v1) *(float2*)(g_aggr + r1 * HID + col) = make_float2(z2, z3);
        float s0 = (v0 ? z0 : 0.f) + (v1 ? z2 : 0.f);
        float s1 = (v0 ? z1 : 0.f) + (v1 ? z3 : 0.f);
        float q0 = (v0 ? z0 * z0 : 0.f) + (v1 ? z2 * z2 : 0.f);
        float q1 = (v0 ? z1 * z1 : 0.f) + (v1 ? z3 * z3 : 0.f);
        s[2 * j] = s0; s[2 * j + 1] = s1;
        q[2 * j] = q0; q[2 * j + 1] = q1;
    }
#pragma unroll
    for (int off = 16; off >= 4; off >>= 1) {
#pragma unroll
        for (int i = 0; i < 16; i++) {
            s[i] += __shfl_xor_sync(0xffffffffu, s[i], off);
            q[i] += __shfl_xor_sync(0xffffffffu, q[i], off);
        }
    }
    __syncthreads();
    float* red_s = (float*)smw;
    float* red_q = (float*)smw + 512;
    if (gid == 0) {
#pragma unroll
        for (int j = 0; j < 8; j++) {
            int cl = 8 * j + 2 * tig;
            red_s[w * 64 + cl] = s[2 * j];
            red_s[w * 64 + cl + 1] = s[2 * j + 1];
            red_q[w * 64 + cl] = q[2 * j];
            red_q[w * 64 + cl + 1] = q[2 * j + 1];
        }
    }
    __syncthreads();
    if (tid < HID) {
        int grp = tid >> 6, cl = tid & 63;
        float S = 0.f, Q = 0.f;
#pragma unroll
        for (int m = 0; m < 4; m++) {
            int ww = grp * 4 + m;
            S += red_s[ww * 64 + cl];
            Q += red_q[ww * 64 + cl];
        }
        atomicAdd(&g_bnsum[layer * HID + tid], (double)S);
        atomicAdd(&g_bnsq[layer * HID + tid], (double)Q);
    }
}

// ====== BN stats (in-block) + apply + relu + pooling with block pre-reduction ======
__global__ void k_bnapply(const int* __restrict__ batch,
                          const float* __restrict__ bn_g,
                          const float* __restrict__ bn_b,
                          int layer, int last) {
    __shared__ float sc[HID], sh[HID];
    __shared__ float4 rbuf[256];
    int tid = threadIdx.x;
    if (tid < HID) {
        double mu = g_bnsum[layer * HID + tid] / (double)N_NODES;
        double var = g_bnsq[layer * HID + tid] / (double)N_NODES - mu * mu;
        if (var < 0.0) var = 0.0;
        float scale = bn_g[layer * HID + tid] * rsqrtf((float)var + 1e-5f);
        sc[tid] = scale;
        sh[tid] = bn_b[layer * HID + tid] - (float)mu * scale;
    }
    __syncthreads();
    int idx = blockIdx.x * 256 + tid;          // exactly N_NODES*32
    int node = idx >> 5, j = idx & 31;
    float4 z = ((const float4*)g_aggr)[idx];
    float4 s4 = ((const float4*)sc)[j];
    float4 h4 = ((const float4*)sh)[j];
    float4 h;
    h.x = fmaxf(z.x * s4.x + h4.x, 0.f);
    h.y = fmaxf(z.y * s4.y + h4.y, 0.f);
    h.z = fmaxf(z.z * s4.z + h4.z, 0.f);
    h.w = fmaxf(z.w * s4.w + h4.w, 0.f);
    ((float4*)g_h)[idx] = h;

    int nfirst = blockIdx.x * 8;
    int g0 = batch[nfirst];
    int g7 = batch[nfirst + 7];
    float* target = last ? g_gsum : g_vnup;
    if (g0 == g7) {
        rbuf[tid] = h;
        __syncthreads();
        if (tid < 128) {
            float4 o = rbuf[tid + 128];
            rbuf[tid].x += o.x; rbuf[tid].y += o.y;
            rbuf[tid].z += o.z; rbuf[tid].w += o.w;
        }
        __syncthreads();
        if (tid < 64) {
            float4 o = rbuf[tid + 64];
            rbuf[tid].x += o.x; rbuf[tid].y += o.y;
            rbuf[tid].z += o.z; rbuf[tid].w += o.w;
        }
        __syncthreads();
        if (tid < 32) {
            float4 o = rbuf[tid + 32];
            float4 r = rbuf[tid];
            r.x += o.x; r.y += o.y; r.z += o.z; r.w += o.w;
            red_add_v4(target + g0 * HID + tid * 4, r);
        }
        if (last && tid == 0) atomicAdd(&g_gcnt[g0], 8);
    } else {
        int g = batch[node];
        red_add_v4(target + g * HID + j * 4, h);
        if (last && j == 0) atomicAdd(&g_gcnt[g], 1);
    }
}

// ================= virtual-node MLP =================
__global__ void k_vn(const float* __restrict__ W1, const float* __restrict__ b1,
                     const float* __restrict__ W2, const float* __restrict__ b2) {
    __shared__ float up[HID];
    __shared__ float t[HID];
    int g = blockIdx.x, j = threadIdx.x;
    up[j] = g_vnup[g * HID + j];
    g_vnup[g * HID + j] = 0.f;
    __syncthreads();
    float s = b1[j];
    for (int k = 0; k < HID; k++) s += up[k] * W1[k * HID + j];
    t[j] = fmaxf(s, 0.f);
    __syncthreads();
    float s2 = b2[j];
    for (int k = 0; k < HID; k++) s2 += t[k] * W2[k * HID + j];
    g_vn[g * HID + j] += s2;
}

// ============ classifier head (also restores g_deg = 0 for the next call) ==========
__global__ void k_cls(const float* __restrict__ W1, const float* __restrict__ b1,
                      const float* __restrict__ W2, const float* __restrict__ b2,
                      float* __restrict__ out) {
    __shared__ float gv[HID];
    __shared__ float t[HID];
    __shared__ float red[HID];
    int g = blockIdx.x, j = threadIdx.x;
    for (int i = g * HID + j; i < N_NODES; i += NUM_GRAPHS * HID) g_deg[i] = 0;
    float inv = 1.f / fmaxf((float)g_gcnt[g], 1.f);
    gv[j] = g_gsum[g * HID + j] * inv;
    __syncthreads();
    float s = b1[j];
    for (int k = 0; k < HID; k++) s += gv[k] * W1[k * HID + j];
    t[j] = fmaxf(s, 0.f);
    __syncthreads();
    red[j] = t[j] * W2[j];
    __syncthreads();
    for (int off = 64; off > 0; off >>= 1) {
        if (j < off) red[j] += red[j + off];
        __syncthreads();
    }
    if (j == 0) out[g] = red[0] + b2[0];
}

// ================= host launcher =================
extern "C" void kernel_launch(void* const* d_in, const int* in_sizes, int n_in,
                              void* d_out, int out_size) {
    const float* x    = (const float*)d_in[0];
    const float* ea   = (const float*)d_in[1];
    const int*   ei   = (const int*)d_in[2];
    const int*   batch= (const int*)d_in[3];
    const float* W_in = (const float*)d_in[4];
    const float* b_in = (const float*)d_in[5];
    const float* W_e  = (const float*)d_in[6];
    const float* b_e  = (const float*)d_in[7];
    const float* cW1  = (const float*)d_in[8];
    const float* cb1  = (const float*)d_in[9];
    const float* cW2  = (const float*)d_in[10];
    const float* cb2  = (const float*)d_in[11];
    const float* bng  = (const float*)d_in[12];
    const float* bnb  = (const float*)d_in[13];
    const float* vW1  = (const float*)d_in[14];
    const float* vb1  = (const float*)d_in[15];
    const float* vW2  = (const float*)d_in[16];
    const float* vb2  = (const float*)d_in[17];
    const float* clW1 = (const float*)d_in[18];
    const float* clb1 = (const float*)d_in[19];
    const float* clW2 = (const float*)d_in[20];
    const float* clb2 = (const float*)d_in[21];
    float* out = (float*)d_out;

    // idempotent host-side attribute sets (no stream op; safe under graph capture)
    cudaFuncSetAttribute(k_layer_mma, cudaFuncAttributeMaxDynamicSharedMemorySize,
                         SMEM_MMA_BYTES);
    cudaFuncSetAttribute(k_input_mma, cudaFuncAttributeMaxDynamicSharedMemorySize,
                         SMEM_IN_BYTES);

    const int NODE_BLOCKS = (N_NODES + 63) / 64;      // 782
    const int ELEM_BLOCKS = (N_NODES * 32) / 256;     // 6250 (exact)
    const int WARP_BLOCKS = (N_NODES + 7) / 8;        // 6250 (warp per node)
    const int EDGE_BLOCKS = N_EDGES / 256;            // 3125 (exact)

    // weight pre-pack + CSR build (g_deg all-zero at entry; restored by k_cls)
    k_wprep<<<9, 256>>>(cW1, cW2, W_in);
    k_hist<<<EDGE_BLOCKS, 256>>>(ei);
    k_scan<<<1, 1024>>>();
    k_scatter<<<EDGE_BLOCKS, 256>>>(ei, ea, batch);

    k_input_mma<<<NODE_BLOCKS, 256, SMEM_IN_BYTES>>>(x, b_in);
    for (int L = 0; L < NUM_LAYERS; L++) {
        if (L == 0) k_gather<0><<<WARP_BLOCKS, 256>>>(W_e, b_e);
        else        k_gather<1><<<WARP_BLOCKS, 256>>>(W_e, b_e);
        k_layer_mma<<<NODE_BLOCKS, 256, SMEM_MMA_BYTES>>>(
            cb1 + L * HID, cb2 + L * HID, batch, (L > 0) ? 1 : 0, L);
        k_bnapply<<<ELEM_BLOCKS, 256>>>(batch, bng, bnb, L,
                                        (L == NUM_LAYERS - 1) ? 1 : 0);
        if (L != NUM_LAYERS - 1) k_vn<<<NUM_GRAPHS, HID>>>(vW1, vb1, vW2, vb2);
    }
    k_cls<<<NUM_GRAPHS, HID>>>(clW1, clb1, clW2, clb2, out);
}